// round 1
// baseline (speedup 1.0000x reference)
#include <cuda_runtime.h>
#include <math.h>

#define HIDDEN   256
#define HEADS    8
#define HEAD_DIM 32
#define NGRAPH   16
#define MAXN     4096
#define LN_EPS   1e-5f
#define ATT_SCALE 0.17677669529663687f  /* 32^-0.5 */

// ---------------- device scratch (no allocation allowed) ----------------
__device__ float g_h  [MAXN * HIDDEN];
__device__ float g_q  [MAXN * HIDDEN];
__device__ float g_k  [MAXN * HIDDEN];
__device__ float g_v  [MAXN * HIDDEN];
__device__ float g_att[MAXN * HIDDEN];
__device__ int   g_batch[MAXN];
__device__ int   g_gstart[NGRAPH + 1];

// ---------------------------------------------------------------------------
// Kernel 1: batch dtype probe (int32 vs int64), normalize to int32,
// per-graph segment offsets (prefix sum). Single block, 256 threads.
//
// Detection: if data is int64 (little endian, values 0..15), every odd 32-bit
// word is a zero high-half. If int32 and sorted with any nonzero value, some
// odd word is nonzero (sorted => a nonzero at even i implies i+1 nonzero,
// except i=4094 whose neighbor 4095 is odd anyway). All-zero data falls to
// the int32 path, which reads identical zeros either way.
// ---------------------------------------------------------------------------
__global__ void prep_batch_kernel(const int* __restrict__ raw, int n) {
    __shared__ int s_odd, s_even;
    __shared__ int s_cnt[NGRAPH];
    int tid = threadIdx.x;
    if (tid == 0) { s_odd = 0; s_even = 0; }
    if (tid < NGRAPH) s_cnt[tid] = 0;
    __syncthreads();

    int odd = 0, even = 0;
    for (int i = tid; i < n; i += blockDim.x) {
        int v = raw[i];
        if (v != 0) { if (i & 1) odd = 1; else even = 1; }
    }
    if (odd)  atomicOr(&s_odd, 1);
    if (even) atomicOr(&s_even, 1);
    __syncthreads();

    bool is64 = (s_odd == 0) && (s_even != 0);
    for (int i = tid; i < n; i += blockDim.x) {
        int v = is64 ? raw[2 * i] : raw[i];
        v = min(max(v, 0), NGRAPH - 1);
        g_batch[i] = v;
        atomicAdd(&s_cnt[v], 1);
    }
    __syncthreads();
    if (tid == 0) {
        int acc = 0;
        for (int g = 0; g < NGRAPH; g++) { g_gstart[g] = acc; acc += s_cnt[g]; }
        g_gstart[NGRAPH] = acc;
    }
}

// ---------------------------------------------------------------------------
// Kernel 2: LayerNorm. One block per row, 256 threads (== HIDDEN).
// ---------------------------------------------------------------------------
__global__ void ln_kernel(const float* __restrict__ x,
                          const float* __restrict__ gamma,
                          const float* __restrict__ beta,
                          float* __restrict__ h) {
    int row = blockIdx.x;
    int tid = threadIdx.x;
    float v = x[row * HIDDEN + tid];

    __shared__ float s1[8], s2[8];
    __shared__ float s_mu, s_rstd;
    float a = v, b = v * v;
    #pragma unroll
    for (int o = 16; o > 0; o >>= 1) {
        a += __shfl_xor_sync(0xffffffffu, a, o);
        b += __shfl_xor_sync(0xffffffffu, b, o);
    }
    if ((tid & 31) == 0) { s1[tid >> 5] = a; s2[tid >> 5] = b; }
    __syncthreads();
    if (tid == 0) {
        float sa = 0.f, sb = 0.f;
        #pragma unroll
        for (int i = 0; i < 8; i++) { sa += s1[i]; sb += s2[i]; }
        float mu  = sa * (1.0f / HIDDEN);
        float var = sb * (1.0f / HIDDEN) - mu * mu;
        s_mu = mu;
        s_rstd = rsqrtf(var + LN_EPS);
    }
    __syncthreads();
    h[row * HIDDEN + tid] = (v - s_mu) * s_rstd * gamma[tid] + beta[tid];
}

// ---------------------------------------------------------------------------
// Kernel 3: fp32 SGEMM, C[M,256] = A[M,256] @ W[256,256] + bias (+ residual).
// 64x64 block tile, BK=16, 256 threads, 4x4 microtile.
// M and N are multiples of 64, K=256 — no bounds checks needed.
// ---------------------------------------------------------------------------
template <bool RES>
__global__ void __launch_bounds__(256)
gemm_kernel(const float* __restrict__ A, const float* __restrict__ W,
            const float* __restrict__ bias, const float* __restrict__ res,
            float* __restrict__ C) {
    const int K = HIDDEN, Nc = HIDDEN;
    __shared__ float As[16][68];   // [k][m], padded stride to reduce conflicts
    __shared__ float Bs[16][64];   // [k][n]

    int tid = threadIdx.x;
    int bm = blockIdx.y * 64;
    int bn = blockIdx.x * 64;
    int tx = tid & 15;        // col group (x4)
    int ty = tid >> 4;        // row group (x4)

    int arow  = tid >> 2;     // 0..63
    int acol4 = tid & 3;      // float4 index within 16 K-cols
    int brow  = tid >> 4;     // 0..15
    int bcol4 = tid & 15;     // float4 index within 64 N-cols

    float acc[4][4] = {};

    for (int k0 = 0; k0 < K; k0 += 16) {
        float4 av = *(const float4*)&A[(bm + arow) * K + k0 + acol4 * 4];
        float4 bv = *(const float4*)&W[(k0 + brow) * Nc + bn + bcol4 * 4];
        __syncthreads();
        As[acol4 * 4 + 0][arow] = av.x;
        As[acol4 * 4 + 1][arow] = av.y;
        As[acol4 * 4 + 2][arow] = av.z;
        As[acol4 * 4 + 3][arow] = av.w;
        *(float4*)&Bs[brow][bcol4 * 4] = bv;
        __syncthreads();
        #pragma unroll
        for (int kk = 0; kk < 16; kk++) {
            float4 a4 = *(const float4*)&As[kk][ty * 4];
            float4 b4 = *(const float4*)&Bs[kk][tx * 4];
            float ar[4] = {a4.x, a4.y, a4.z, a4.w};
            float br[4] = {b4.x, b4.y, b4.z, b4.w};
            #pragma unroll
            for (int i = 0; i < 4; i++)
                #pragma unroll
                for (int j = 0; j < 4; j++)
                    acc[i][j] = fmaf(ar[i], br[j], acc[i][j]);
        }
    }

    float4 bb = *(const float4*)&bias[bn + tx * 4];
    #pragma unroll
    for (int i = 0; i < 4; i++) {
        int row = bm + ty * 4 + i;
        float4 c = make_float4(acc[i][0] + bb.x, acc[i][1] + bb.y,
                               acc[i][2] + bb.z, acc[i][3] + bb.w);
        if (RES) {
            float4 r = *(const float4*)&res[row * Nc + bn + tx * 4];
            c.x += r.x; c.y += r.y; c.z += r.z; c.w += r.w;
        }
        *(float4*)&C[row * Nc + bn + tx * 4] = c;
    }
}

// ---------------------------------------------------------------------------
// Kernel 4: block-diagonal attention. grid = (NGRAPH, HEADS), 256 threads.
// Each thread owns one query row (strided if segment > 256 rows).
// 32-key K/V tiles staged in SMEM; online softmax; fp32 throughout.
// ---------------------------------------------------------------------------
__global__ void __launch_bounds__(256)
attn_kernel() {
    int g = blockIdx.x, hh = blockIdx.y;
    int start = g_gstart[g], end = g_gstart[g + 1];
    int tid = threadIdx.x;

    __shared__ float Ks[32][32];
    __shared__ float Vs[32][32];

    for (int i0 = start; i0 < end; i0 += 256) {
        int i = i0 + tid;
        bool active = (i < end);

        float q[32];
        float acc[32];
        #pragma unroll
        for (int d = 0; d < 32; d++) { q[d] = 0.f; acc[d] = 0.f; }
        float mrun = -1e30f, lrun = 0.f;

        if (active) {
            const float4* qp = (const float4*)&g_q[i * HIDDEN + hh * HEAD_DIM];
            #pragma unroll
            for (int d4 = 0; d4 < 8; d4++) {
                float4 t = qp[d4];
                q[d4 * 4 + 0] = t.x; q[d4 * 4 + 1] = t.y;
                q[d4 * 4 + 2] = t.z; q[d4 * 4 + 3] = t.w;
            }
        }

        for (int t0 = start; t0 < end; t0 += 32) {
            int tn = min(32, end - t0);
            // cooperative tile load: 32 rows x 32 floats, 256 thr x 1 float4
            int r  = tid >> 3;
            int c4 = tid & 7;
            int j  = t0 + r;
            float4 kv = make_float4(0.f, 0.f, 0.f, 0.f);
            float4 vv = make_float4(0.f, 0.f, 0.f, 0.f);
            if (j < end) {
                kv = *(const float4*)&g_k[j * HIDDEN + hh * HEAD_DIM + c4 * 4];
                vv = *(const float4*)&g_v[j * HIDDEN + hh * HEAD_DIM + c4 * 4];
            }
            __syncthreads();
            *(float4*)&Ks[r][c4 * 4] = kv;
            *(float4*)&Vs[r][c4 * 4] = vv;
            __syncthreads();

            if (active) {
                float sc[32];
                #pragma unroll
                for (int jj = 0; jj < 32; jj++) {
                    float s = 0.f;
                    #pragma unroll
                    for (int d4 = 0; d4 < 8; d4++) {
                        float4 kk4 = *(const float4*)&Ks[jj][d4 * 4];
                        s = fmaf(q[d4 * 4 + 0], kk4.x, s);
                        s = fmaf(q[d4 * 4 + 1], kk4.y, s);
                        s = fmaf(q[d4 * 4 + 2], kk4.z, s);
                        s = fmaf(q[d4 * 4 + 3], kk4.w, s);
                    }
                    sc[jj] = (jj < tn) ? s * ATT_SCALE : -1e30f;
                }
                float tmax = -1e30f;
                #pragma unroll
                for (int jj = 0; jj < 32; jj++) tmax = fmaxf(tmax, sc[jj]);
                float newm = fmaxf(mrun, tmax);
                float corr = __expf(mrun - newm);
                lrun *= corr;
                #pragma unroll
                for (int d = 0; d < 32; d++) acc[d] *= corr;
                mrun = newm;
                #pragma unroll
                for (int jj = 0; jj < 32; jj++) {
                    float p = __expf(sc[jj] - mrun);
                    lrun += p;
                    #pragma unroll
                    for (int d4 = 0; d4 < 8; d4++) {
                        float4 vv4 = *(const float4*)&Vs[jj][d4 * 4];
                        acc[d4 * 4 + 0] = fmaf(p, vv4.x, acc[d4 * 4 + 0]);
                        acc[d4 * 4 + 1] = fmaf(p, vv4.y, acc[d4 * 4 + 1]);
                        acc[d4 * 4 + 2] = fmaf(p, vv4.z, acc[d4 * 4 + 2]);
                        acc[d4 * 4 + 3] = fmaf(p, vv4.w, acc[d4 * 4 + 3]);
                    }
                }
            }
        }

        if (active) {
            float inv_l = 1.0f / lrun;
            float4* op = (float4*)&g_att[i * HIDDEN + hh * HEAD_DIM];
            #pragma unroll
            for (int d4 = 0; d4 < 8; d4++) {
                op[d4] = make_float4(acc[d4 * 4 + 0] * inv_l,
                                     acc[d4 * 4 + 1] * inv_l,
                                     acc[d4 * 4 + 2] * inv_l,
                                     acc[d4 * 4 + 3] * inv_l);
            }
        }
    }
}

// ---------------------------------------------------------------------------
extern "C" void kernel_launch(void* const* d_in, const int* in_sizes, int n_in,
                              void* d_out, int out_size) {
    const float* x     = (const float*)d_in[0];
    const int*   batch = (const int*)  d_in[1];
    const float* Wq    = (const float*)d_in[2];
    const float* bq    = (const float*)d_in[3];
    const float* Wk    = (const float*)d_in[4];
    const float* bk    = (const float*)d_in[5];
    const float* Wv    = (const float*)d_in[6];
    const float* bv    = (const float*)d_in[7];
    const float* Wo    = (const float*)d_in[8];
    const float* bo    = (const float*)d_in[9];
    const float* gamma = (const float*)d_in[10];
    const float* beta  = (const float*)d_in[11];
    float* out = (float*)d_out;

    int n = in_sizes[0] / HIDDEN;   // 4096

    float *ph, *pq, *pk, *pv, *patt;
    cudaGetSymbolAddress((void**)&ph,   g_h);
    cudaGetSymbolAddress((void**)&pq,   g_q);
    cudaGetSymbolAddress((void**)&pk,   g_k);
    cudaGetSymbolAddress((void**)&pv,   g_v);
    cudaGetSymbolAddress((void**)&patt, g_att);

    prep_batch_kernel<<<1, 256>>>(batch, n);
    ln_kernel<<<n, 256>>>(x, gamma, beta, ph);

    dim3 gg(HIDDEN / 64, n / 64);
    gemm_kernel<false><<<gg, 256>>>(ph, Wq, bq, nullptr, pq);
    gemm_kernel<false><<<gg, 256>>>(ph, Wk, bk, nullptr, pk);
    gemm_kernel<false><<<gg, 256>>>(ph, Wv, bv, nullptr, pv);

    attn_kernel<<<dim3(NGRAPH, HEADS), 256>>>();

    gemm_kernel<true><<<gg, 256>>>(patt, Wo, bo, x, out);
}

// round 2
// speedup vs baseline: 1.3140x; 1.3140x over previous
#include <cuda_runtime.h>
#include <math.h>
#include <stdint.h>

#define HIDDEN   256
#define HEADS    8
#define HEAD_DIM 32
#define NGRAPH   16
#define MAXN     4096
#define LN_EPS   1e-5f
#define ATT_SCALE 0.17677669529663687f  /* 32^-0.5 */

// ---------------- device scratch (no allocation allowed) ----------------
__device__ float g_h  [MAXN * HIDDEN];
__device__ float g_q  [MAXN * HIDDEN];
__device__ float g_k  [MAXN * HIDDEN];
__device__ float g_v  [MAXN * HIDDEN];
__device__ float g_att[MAXN * HIDDEN];
__device__ int   g_batch[MAXN];
__device__ int   g_gstart[NGRAPH + 1];

// ---------------------------------------------------------------------------
// Kernel 1: batch dtype probe (int32 vs int64), normalize to int32,
// per-graph segment offsets (prefix sum). Single block, 256 threads.
// ---------------------------------------------------------------------------
__global__ void prep_batch_kernel(const int* __restrict__ raw, int n) {
    __shared__ int s_odd, s_even;
    __shared__ int s_cnt[NGRAPH];
    int tid = threadIdx.x;
    if (tid == 0) { s_odd = 0; s_even = 0; }
    if (tid < NGRAPH) s_cnt[tid] = 0;
    __syncthreads();

    int odd = 0, even = 0;
    for (int i = tid; i < n; i += blockDim.x) {
        int v = raw[i];
        if (v != 0) { if (i & 1) odd = 1; else even = 1; }
    }
    if (odd)  atomicOr(&s_odd, 1);
    if (even) atomicOr(&s_even, 1);
    __syncthreads();

    bool is64 = (s_odd == 0) && (s_even != 0);
    for (int i = tid; i < n; i += blockDim.x) {
        int v = is64 ? raw[2 * i] : raw[i];
        v = min(max(v, 0), NGRAPH - 1);
        g_batch[i] = v;
        atomicAdd(&s_cnt[v], 1);
    }
    __syncthreads();
    if (tid == 0) {
        int acc = 0;
        for (int g = 0; g < NGRAPH; g++) { g_gstart[g] = acc; acc += s_cnt[g]; }
        g_gstart[NGRAPH] = acc;
    }
}

// ---------------------------------------------------------------------------
// Kernel 2: LayerNorm. One block per row, 256 threads (== HIDDEN).
// ---------------------------------------------------------------------------
__global__ void ln_kernel(const float* __restrict__ x,
                          const float* __restrict__ gamma,
                          const float* __restrict__ beta,
                          float* __restrict__ h) {
    int row = blockIdx.x;
    int tid = threadIdx.x;
    float v = x[row * HIDDEN + tid];

    __shared__ float s1[8], s2[8];
    __shared__ float s_mu, s_rstd;
    float a = v, b = v * v;
    #pragma unroll
    for (int o = 16; o > 0; o >>= 1) {
        a += __shfl_xor_sync(0xffffffffu, a, o);
        b += __shfl_xor_sync(0xffffffffu, b, o);
    }
    if ((tid & 31) == 0) { s1[tid >> 5] = a; s2[tid >> 5] = b; }
    __syncthreads();
    if (tid == 0) {
        float sa = 0.f, sb = 0.f;
        #pragma unroll
        for (int i = 0; i < 8; i++) { sa += s1[i]; sb += s2[i]; }
        float mu  = sa * (1.0f / HIDDEN);
        float var = sb * (1.0f / HIDDEN) - mu * mu;
        s_mu = mu;
        s_rstd = rsqrtf(var + LN_EPS);
    }
    __syncthreads();
    h[row * HIDDEN + tid] = (v - s_mu) * s_rstd * gamma[tid] + beta[tid];
}

// ---------------------------------------------------------------------------
// tf32 tensor-core GEMM: C[4096,256] = A @ W + bias (+ residual)
// Block tile 128(M) x 64(N), BK=32, 256 threads = 8 warps (4x2),
// warp tile 32x32 via mma.sync.m16n8k8.tf32 (2x4 fragments).
// A smem: XOR swizzle (conflict-free frag loads); B smem: stride-72 pad.
// ---------------------------------------------------------------------------
__device__ __forceinline__ uint32_t f2tf(float f) {
    uint32_t r;
    asm("cvt.rna.tf32.f32 %0, %1;" : "=r"(r) : "f"(f));
    return r;
}

__device__ __forceinline__ void mma_tf32(float* c, const uint32_t* a, const uint32_t* b) {
    asm volatile(
        "mma.sync.aligned.m16n8k8.row.col.f32.tf32.tf32.f32 "
        "{%0,%1,%2,%3}, {%4,%5,%6,%7}, {%8,%9}, {%0,%1,%2,%3};"
        : "+f"(c[0]), "+f"(c[1]), "+f"(c[2]), "+f"(c[3])
        : "r"(a[0]), "r"(a[1]), "r"(a[2]), "r"(a[3]), "r"(b[0]), "r"(b[1]));
}

template <bool RES>
__device__ __forceinline__ void gemm_core(const float* __restrict__ A,
                                          const float* __restrict__ W,
                                          const float* __restrict__ bias,
                                          const float* __restrict__ res,
                                          float* __restrict__ C) {
    __shared__ uint32_t As[128 * 32];   // tf32, swizzled, 16KB
    __shared__ uint32_t Bs[32 * 72];    // tf32, padded stride 72, 9KB

    const int tid  = threadIdx.x;
    const int lane = tid & 31;
    const int wid  = tid >> 5;
    const int wm   = wid & 3;          // warp M slice (x32)
    const int wn   = wid >> 2;         // warp N slice (x32)
    const int bm   = blockIdx.y * 128;
    const int bn   = blockIdx.x * 64;

    // global->smem assignment
    const int ar  = tid >> 1;          // A row 0..127
    const int ach = tid & 1;           // A col4 half (4 float4 each)
    const int bk  = tid >> 4;          // B k row 0..15 (and +16)
    const int bn4 = tid & 15;          // B float4 col 0..15

    const int g   = lane >> 2;         // fragment group row
    const int t   = lane & 3;          // fragment thread-in-group
    const int swz = g << 2;            // A smem swizzle for this lane

    float acc[2][4][4] = {};

    for (int k0 = 0; k0 < HIDDEN; k0 += 32) {
        // ---- global loads into registers ----
        float4 av[4];
        const float4* Ap = (const float4*)&A[(bm + ar) * HIDDEN + k0];
        #pragma unroll
        for (int i = 0; i < 4; i++) av[i] = Ap[ach * 4 + i];
        float4 bv[2];
        #pragma unroll
        for (int i = 0; i < 2; i++)
            bv[i] = *(const float4*)&W[(k0 + bk + i * 16) * HIDDEN + bn + bn4 * 4];

        __syncthreads();
        // ---- store A (swizzled, tf32) ----
        #pragma unroll
        for (int i = 0; i < 4; i++) {
            int c4 = ach * 4 + i;
            int phys = ar * 8 + (c4 ^ (ar & 7));   // float4 units
            uint4 w4 = make_uint4(f2tf(av[i].x), f2tf(av[i].y),
                                  f2tf(av[i].z), f2tf(av[i].w));
            *(uint4*)&As[phys * 4] = w4;
        }
        // ---- store B (padded, tf32) ----
        #pragma unroll
        for (int i = 0; i < 2; i++) {
            int k = bk + i * 16;
            uint4 w4 = make_uint4(f2tf(bv[i].x), f2tf(bv[i].y),
                                  f2tf(bv[i].z), f2tf(bv[i].w));
            *(uint4*)&Bs[k * 72 + bn4 * 4] = w4;
        }
        __syncthreads();

        // ---- compute: 4 k-steps of 8 ----
        #pragma unroll
        for (int kk = 0; kk < 4; kk++) {
            uint32_t afr[2][4];
            #pragma unroll
            for (int fm = 0; fm < 2; fm++) {
                int r0 = wm * 32 + fm * 16 + g;
                int r1 = r0 + 8;
                int c0 = kk * 8 + t;
                int c1 = c0 + 4;
                afr[fm][0] = As[r0 * 32 + (c0 ^ swz)];
                afr[fm][1] = As[r1 * 32 + (c0 ^ swz)];
                afr[fm][2] = As[r0 * 32 + (c1 ^ swz)];
                afr[fm][3] = As[r1 * 32 + (c1 ^ swz)];
            }
            uint32_t bfr[4][2];
            #pragma unroll
            for (int fn = 0; fn < 4; fn++) {
                int n  = wn * 32 + fn * 8 + g;
                int kb = kk * 8 + t;
                bfr[fn][0] = Bs[kb * 72 + n];
                bfr[fn][1] = Bs[(kb + 4) * 72 + n];
            }
            #pragma unroll
            for (int fm = 0; fm < 2; fm++)
                #pragma unroll
                for (int fn = 0; fn < 4; fn++)
                    mma_tf32(acc[fm][fn], afr[fm], bfr[fn]);
        }
    }

    // ---- epilogue: bias (+ residual), float2 stores ----
    #pragma unroll
    for (int fm = 0; fm < 2; fm++) {
        int row0 = bm + wm * 32 + fm * 16 + g;
        int row1 = row0 + 8;
        #pragma unroll
        for (int fn = 0; fn < 4; fn++) {
            int col = bn + wn * 32 + fn * 8 + t * 2;
            float2 bb = *(const float2*)&bias[col];
            float2 c0 = make_float2(acc[fm][fn][0] + bb.x, acc[fm][fn][1] + bb.y);
            float2 c1 = make_float2(acc[fm][fn][2] + bb.x, acc[fm][fn][3] + bb.y);
            if (RES) {
                float2 r0 = *(const float2*)&res[row0 * HIDDEN + col];
                float2 r1 = *(const float2*)&res[row1 * HIDDEN + col];
                c0.x += r0.x; c0.y += r0.y;
                c1.x += r1.x; c1.y += r1.y;
            }
            *(float2*)&C[row0 * HIDDEN + col] = c0;
            *(float2*)&C[row1 * HIDDEN + col] = c1;
        }
    }
}

__global__ void __launch_bounds__(256)
gemm_qkv_kernel(const float* __restrict__ A,
                const float* __restrict__ Wq, const float* __restrict__ bq, float* __restrict__ Cq,
                const float* __restrict__ Wk, const float* __restrict__ bk, float* __restrict__ Ck,
                const float* __restrict__ Wv, const float* __restrict__ bv, float* __restrict__ Cv) {
    const float* W; const float* b; float* C;
    if (blockIdx.z == 0)      { W = Wq; b = bq; C = Cq; }
    else if (blockIdx.z == 1) { W = Wk; b = bk; C = Ck; }
    else                      { W = Wv; b = bv; C = Cv; }
    gemm_core<false>(A, W, b, nullptr, C);
}

__global__ void __launch_bounds__(256)
gemm_o_kernel(const float* __restrict__ A, const float* __restrict__ W,
              const float* __restrict__ bias, const float* __restrict__ res,
              float* __restrict__ C) {
    gemm_core<true>(A, W, bias, res, C);
}

// ---------------------------------------------------------------------------
// Kernel 4: block-diagonal attention. grid = (NGRAPH, HEADS), 256 threads.
// ---------------------------------------------------------------------------
__global__ void __launch_bounds__(256)
attn_kernel() {
    int g = blockIdx.x, hh = blockIdx.y;
    int start = g_gstart[g], end = g_gstart[g + 1];
    int tid = threadIdx.x;

    __shared__ float Ks[32][32];
    __shared__ float Vs[32][32];

    for (int i0 = start; i0 < end; i0 += 256) {
        int i = i0 + tid;
        bool active = (i < end);

        float q[32];
        float acc[32];
        #pragma unroll
        for (int d = 0; d < 32; d++) { q[d] = 0.f; acc[d] = 0.f; }
        float mrun = -1e30f, lrun = 0.f;

        if (active) {
            const float4* qp = (const float4*)&g_q[i * HIDDEN + hh * HEAD_DIM];
            #pragma unroll
            for (int d4 = 0; d4 < 8; d4++) {
                float4 tq = qp[d4];
                q[d4 * 4 + 0] = tq.x; q[d4 * 4 + 1] = tq.y;
                q[d4 * 4 + 2] = tq.z; q[d4 * 4 + 3] = tq.w;
            }
        }

        for (int t0 = start; t0 < end; t0 += 32) {
            int tn = min(32, end - t0);
            int r  = tid >> 3;
            int c4 = tid & 7;
            int j  = t0 + r;
            float4 kv = make_float4(0.f, 0.f, 0.f, 0.f);
            float4 vv = make_float4(0.f, 0.f, 0.f, 0.f);
            if (j < end) {
                kv = *(const float4*)&g_k[j * HIDDEN + hh * HEAD_DIM + c4 * 4];
                vv = *(const float4*)&g_v[j * HIDDEN + hh * HEAD_DIM + c4 * 4];
            }
            __syncthreads();
            *(float4*)&Ks[r][c4 * 4] = kv;
            *(float4*)&Vs[r][c4 * 4] = vv;
            __syncthreads();

            if (active) {
                float sc[32];
                #pragma unroll
                for (int jj = 0; jj < 32; jj++) {
                    float s = 0.f;
                    #pragma unroll
                    for (int d4 = 0; d4 < 8; d4++) {
                        float4 kk4 = *(const float4*)&Ks[jj][d4 * 4];
                        s = fmaf(q[d4 * 4 + 0], kk4.x, s);
                        s = fmaf(q[d4 * 4 + 1], kk4.y, s);
                        s = fmaf(q[d4 * 4 + 2], kk4.z, s);
                        s = fmaf(q[d4 * 4 + 3], kk4.w, s);
                    }
                    sc[jj] = (jj < tn) ? s * ATT_SCALE : -1e30f;
                }
                float tmax = -1e30f;
                #pragma unroll
                for (int jj = 0; jj < 32; jj++) tmax = fmaxf(tmax, sc[jj]);
                float newm = fmaxf(mrun, tmax);
                float corr = __expf(mrun - newm);
                lrun *= corr;
                #pragma unroll
                for (int d = 0; d < 32; d++) acc[d] *= corr;
                mrun = newm;
                #pragma unroll
                for (int jj = 0; jj < 32; jj++) {
                    float p = __expf(sc[jj] - mrun);
                    lrun += p;
                    #pragma unroll
                    for (int d4 = 0; d4 < 8; d4++) {
                        float4 vv4 = *(const float4*)&Vs[jj][d4 * 4];
                        acc[d4 * 4 + 0] = fmaf(p, vv4.x, acc[d4 * 4 + 0]);
                        acc[d4 * 4 + 1] = fmaf(p, vv4.y, acc[d4 * 4 + 1]);
                        acc[d4 * 4 + 2] = fmaf(p, vv4.z, acc[d4 * 4 + 2]);
                        acc[d4 * 4 + 3] = fmaf(p, vv4.w, acc[d4 * 4 + 3]);
                    }
                }
            }
        }

        if (active) {
            float inv_l = 1.0f / lrun;
            float4* op = (float4*)&g_att[i * HIDDEN + hh * HEAD_DIM];
            #pragma unroll
            for (int d4 = 0; d4 < 8; d4++) {
                op[d4] = make_float4(acc[d4 * 4 + 0] * inv_l,
                                     acc[d4 * 4 + 1] * inv_l,
                                     acc[d4 * 4 + 2] * inv_l,
                                     acc[d4 * 4 + 3] * inv_l);
            }
        }
    }
}

// ---------------------------------------------------------------------------
extern "C" void kernel_launch(void* const* d_in, const int* in_sizes, int n_in,
                              void* d_out, int out_size) {
    const float* x     = (const float*)d_in[0];
    const int*   batch = (const int*)  d_in[1];
    const float* Wq    = (const float*)d_in[2];
    const float* bq    = (const float*)d_in[3];
    const float* Wk    = (const float*)d_in[4];
    const float* bk    = (const float*)d_in[5];
    const float* Wv    = (const float*)d_in[6];
    const float* bv    = (const float*)d_in[7];
    const float* Wo    = (const float*)d_in[8];
    const float* bo    = (const float*)d_in[9];
    const float* gamma = (const float*)d_in[10];
    const float* beta  = (const float*)d_in[11];
    float* out = (float*)d_out;

    int n = in_sizes[0] / HIDDEN;   // 4096

    float *ph, *pq, *pk, *pv, *patt;
    cudaGetSymbolAddress((void**)&ph,   g_h);
    cudaGetSymbolAddress((void**)&pq,   g_q);
    cudaGetSymbolAddress((void**)&pk,   g_k);
    cudaGetSymbolAddress((void**)&pv,   g_v);
    cudaGetSymbolAddress((void**)&patt, g_att);

    prep_batch_kernel<<<1, 256>>>(batch, n);
    ln_kernel<<<n, 256>>>(x, gamma, beta, ph);

    dim3 gqkv(HIDDEN / 64, n / 128, 3);
    gemm_qkv_kernel<<<gqkv, 256>>>(ph, Wq, bq, pq, Wk, bk, pk, Wv, bv, pv);

    attn_kernel<<<dim3(NGRAPH, HEADS), 256>>>();

    dim3 go(HIDDEN / 64, n / 128, 1);
    gemm_o_kernel<<<go, 256>>>(patt, Wo, bo, x, out);
}

// round 4
// speedup vs baseline: 2.4806x; 1.8878x over previous
#include <cuda_runtime.h>
#include <math.h>
#include <stdint.h>

#define HIDDEN   256
#define HEADS    8
#define HEAD_DIM 32
#define NGRAPH   16
#define MAXN     4096
#define LN_EPS   1e-5f
#define ATT_SCALE 0.17677669529663687f  /* 32^-0.5 */

// ---------------- device scratch (no allocation allowed) ----------------
__device__ float g_h  [MAXN * HIDDEN];
__device__ float g_q  [MAXN * HIDDEN];
__device__ float g_k  [MAXN * HIDDEN];
__device__ float g_v  [MAXN * HIDDEN];
__device__ float g_att[MAXN * HIDDEN];
__device__ int   g_batch[MAXN];
__device__ int   g_gstart[NGRAPH + 1];

// ---------------------------------------------------------------------------
// Kernel 1: batch dtype probe (int32 vs int64), normalize, segment offsets.
// ---------------------------------------------------------------------------
__global__ void prep_batch_kernel(const int* __restrict__ raw, int n) {
    __shared__ int s_odd, s_even;
    __shared__ int s_cnt[NGRAPH];
    int tid = threadIdx.x;
    if (tid == 0) { s_odd = 0; s_even = 0; }
    if (tid < NGRAPH) s_cnt[tid] = 0;
    __syncthreads();

    int odd = 0, even = 0;
    for (int i = tid; i < n; i += blockDim.x) {
        int v = raw[i];
        if (v != 0) { if (i & 1) odd = 1; else even = 1; }
    }
    if (odd)  atomicOr(&s_odd, 1);
    if (even) atomicOr(&s_even, 1);
    __syncthreads();

    bool is64 = (s_odd == 0) && (s_even != 0);
    for (int i = tid; i < n; i += blockDim.x) {
        int v = is64 ? raw[2 * i] : raw[i];
        v = min(max(v, 0), NGRAPH - 1);
        g_batch[i] = v;
        atomicAdd(&s_cnt[v], 1);
    }
    __syncthreads();
    if (tid == 0) {
        int acc = 0;
        for (int g = 0; g < NGRAPH; g++) { g_gstart[g] = acc; acc += s_cnt[g]; }
        g_gstart[NGRAPH] = acc;
    }
}

// ---------------------------------------------------------------------------
// Kernel 2: LayerNorm. One block per row, 256 threads (== HIDDEN).
// ---------------------------------------------------------------------------
__global__ void ln_kernel(const float* __restrict__ x,
                          const float* __restrict__ gamma,
                          const float* __restrict__ beta,
                          float* __restrict__ h) {
    int row = blockIdx.x;
    int tid = threadIdx.x;
    float v = x[row * HIDDEN + tid];

    __shared__ float s1[8], s2[8];
    __shared__ float s_mu, s_rstd;
    float a = v, b = v * v;
    #pragma unroll
    for (int o = 16; o > 0; o >>= 1) {
        a += __shfl_xor_sync(0xffffffffu, a, o);
        b += __shfl_xor_sync(0xffffffffu, b, o);
    }
    if ((tid & 31) == 0) { s1[tid >> 5] = a; s2[tid >> 5] = b; }
    __syncthreads();
    if (tid == 0) {
        float sa = 0.f, sb = 0.f;
        #pragma unroll
        for (int i = 0; i < 8; i++) { sa += s1[i]; sb += s2[i]; }
        float mu  = sa * (1.0f / HIDDEN);
        float var = sb * (1.0f / HIDDEN) - mu * mu;
        s_mu = mu;
        s_rstd = rsqrtf(var + LN_EPS);
    }
    __syncthreads();
    h[row * HIDDEN + tid] = (v - s_mu) * s_rstd * gamma[tid] + beta[tid];
}

// ---------------------------------------------------------------------------
// tf32 helpers
// ---------------------------------------------------------------------------
__device__ __forceinline__ uint32_t f2tf(float f) {
    uint32_t r;
    asm("cvt.rna.tf32.f32 %0, %1;" : "=r"(r) : "f"(f));
    return r;
}

__device__ __forceinline__ void mma_tf32(float* c, const uint32_t* a, const uint32_t* b) {
    asm volatile(
        "mma.sync.aligned.m16n8k8.row.col.f32.tf32.tf32.f32 "
        "{%0,%1,%2,%3}, {%4,%5,%6,%7}, {%8,%9}, {%0,%1,%2,%3};"
        : "+f"(c[0]), "+f"(c[1]), "+f"(c[2]), "+f"(c[3])
        : "r"(a[0]), "r"(a[1]), "r"(a[2]), "r"(a[3]), "r"(b[0]), "r"(b[1]));
}

// ---------------------------------------------------------------------------
// tf32 tensor-core GEMM: C[4096,256] = A @ W + bias (+ residual)
// Block 128x64, BK=32, 8 warps, warp tile 32x32 (2x4 m16n8k8 frags).
// ---------------------------------------------------------------------------
template <bool RES>
__device__ __forceinline__ void gemm_core(const float* __restrict__ A,
                                          const float* __restrict__ W,
                                          const float* __restrict__ bias,
                                          const float* __restrict__ res,
                                          float* __restrict__ C) {
    __shared__ uint32_t As[128 * 32];   // swizzled
    __shared__ uint32_t Bs[32 * 72];    // padded stride 72

    const int tid  = threadIdx.x;
    const int lane = tid & 31;
    const int wid  = tid >> 5;
    const int wm   = wid & 3;
    const int wn   = wid >> 2;
    const int bm   = blockIdx.y * 128;
    const int bn   = blockIdx.x * 64;

    const int ar  = tid >> 1;
    const int ach = tid & 1;
    const int bk  = tid >> 4;
    const int bn4 = tid & 15;

    const int g   = lane >> 2;
    const int t   = lane & 3;
    const int swz = g << 2;

    float acc[2][4][4] = {};

    for (int k0 = 0; k0 < HIDDEN; k0 += 32) {
        float4 av[4];
        const float4* Ap = (const float4*)&A[(bm + ar) * HIDDEN + k0];
        #pragma unroll
        for (int i = 0; i < 4; i++) av[i] = Ap[ach * 4 + i];
        float4 bv[2];
        #pragma unroll
        for (int i = 0; i < 2; i++)
            bv[i] = *(const float4*)&W[(k0 + bk + i * 16) * HIDDEN + bn + bn4 * 4];

        __syncthreads();
        #pragma unroll
        for (int i = 0; i < 4; i++) {
            int c4 = ach * 4 + i;
            int phys = ar * 8 + (c4 ^ (ar & 7));
            uint4 w4 = make_uint4(f2tf(av[i].x), f2tf(av[i].y),
                                  f2tf(av[i].z), f2tf(av[i].w));
            *(uint4*)&As[phys * 4] = w4;
        }
        #pragma unroll
        for (int i = 0; i < 2; i++) {
            int k = bk + i * 16;
            uint4 w4 = make_uint4(f2tf(bv[i].x), f2tf(bv[i].y),
                                  f2tf(bv[i].z), f2tf(bv[i].w));
            *(uint4*)&Bs[k * 72 + bn4 * 4] = w4;
        }
        __syncthreads();

        #pragma unroll
        for (int kk = 0; kk < 4; kk++) {
            uint32_t afr[2][4];
            #pragma unroll
            for (int fm = 0; fm < 2; fm++) {
                int r0 = wm * 32 + fm * 16 + g;
                int r1 = r0 + 8;
                int c0 = kk * 8 + t;
                int c1 = c0 + 4;
                afr[fm][0] = As[r0 * 32 + (c0 ^ swz)];
                afr[fm][1] = As[r1 * 32 + (c0 ^ swz)];
                afr[fm][2] = As[r0 * 32 + (c1 ^ swz)];
                afr[fm][3] = As[r1 * 32 + (c1 ^ swz)];
            }
            uint32_t bfr[4][2];
            #pragma unroll
            for (int fn = 0; fn < 4; fn++) {
                int n  = wn * 32 + fn * 8 + g;
                int kb = kk * 8 + t;
                bfr[fn][0] = Bs[kb * 72 + n];
                bfr[fn][1] = Bs[(kb + 4) * 72 + n];
            }
            #pragma unroll
            for (int fm = 0; fm < 2; fm++)
                #pragma unroll
                for (int fn = 0; fn < 4; fn++)
                    mma_tf32(acc[fm][fn], afr[fm], bfr[fn]);
        }
    }

    #pragma unroll
    for (int fm = 0; fm < 2; fm++) {
        int row0 = bm + wm * 32 + fm * 16 + g;
        int row1 = row0 + 8;
        #pragma unroll
        for (int fn = 0; fn < 4; fn++) {
            int col = bn + wn * 32 + fn * 8 + t * 2;
            float2 bb = *(const float2*)&bias[col];
            float2 c0 = make_float2(acc[fm][fn][0] + bb.x, acc[fm][fn][1] + bb.y);
            float2 c1 = make_float2(acc[fm][fn][2] + bb.x, acc[fm][fn][3] + bb.y);
            if (RES) {
                float2 r0 = *(const float2*)&res[row0 * HIDDEN + col];
                float2 r1 = *(const float2*)&res[row1 * HIDDEN + col];
                c0.x += r0.x; c0.y += r0.y;
                c1.x += r1.x; c1.y += r1.y;
            }
            *(float2*)&C[row0 * HIDDEN + col] = c0;
            *(float2*)&C[row1 * HIDDEN + col] = c1;
        }
    }
}

__global__ void __launch_bounds__(256)
gemm_qkv_kernel(const float* __restrict__ A,
                const float* __restrict__ Wq, const float* __restrict__ bq, float* __restrict__ Cq,
                const float* __restrict__ Wk, const float* __restrict__ bk, float* __restrict__ Ck,
                const float* __restrict__ Wv, const float* __restrict__ bv, float* __restrict__ Cv) {
    const float* W; const float* b; float* C;
    if (blockIdx.z == 0)      { W = Wq; b = bq; C = Cq; }
    else if (blockIdx.z == 1) { W = Wk; b = bk; C = Ck; }
    else                      { W = Wv; b = bv; C = Cv; }
    gemm_core<false>(A, W, b, nullptr, C);
}

__global__ void __launch_bounds__(256)
gemm_o_kernel(const float* __restrict__ A, const float* __restrict__ W,
              const float* __restrict__ bias, const float* __restrict__ res,
              float* __restrict__ C) {
    gemm_core<true>(A, W, bias, res, C);
}

// ---------------------------------------------------------------------------
// Kernel 4: tensor-core flash attention over block-diagonal segments.
// grid = (NGRAPH, HEADS, 8); block = 128 (4 warps x 16 query rows = 64 q/blk).
// Per 32-key tile: S = Q K^T via 16 mma.tf32, warp-level online softmax on
// C-frags, P staged through per-warp smem, O += P V via 16 mma.tf32.
// Smem: Ks[j][d] stride 36 (conflict-free B-frags: bank = 4g+t bijective),
// Vt[d][j] transposed stride 36 (same property), Ps per warp stride 36.
// ---------------------------------------------------------------------------
__global__ void __launch_bounds__(128)
attn_kernel() {
    __shared__ uint32_t Ks[32][36];
    __shared__ uint32_t Vt[32][36];
    __shared__ uint32_t Ps[4][16][36];

    const int gb = blockIdx.x, hh = blockIdx.y;
    const int start = g_gstart[gb], end = g_gstart[gb + 1];
    const int n = end - start;
    const int tid = threadIdx.x, lane = tid & 31, wid = tid >> 5;
    const int gq = lane >> 2, tq = lane & 3;

    for (int qt = blockIdx.z * 64; qt < n; qt += gridDim.z * 64) {
        int q0 = start + qt + wid * 16;
        int r0 = q0 + gq, r1 = r0 + 8;
        bool v0 = r0 < end, v1 = r1 < end;

        uint32_t qa[4][4];
        #pragma unroll
        for (int kk = 0; kk < 4; kk++) {
            int c = hh * HEAD_DIM + kk * 8 + tq;
            qa[kk][0] = v0 ? f2tf(g_q[r0 * HIDDEN + c])     : 0u;
            qa[kk][1] = v1 ? f2tf(g_q[r1 * HIDDEN + c])     : 0u;
            qa[kk][2] = v0 ? f2tf(g_q[r0 * HIDDEN + c + 4]) : 0u;
            qa[kk][3] = v1 ? f2tf(g_q[r1 * HIDDEN + c + 4]) : 0u;
        }

        float o[4][4] = {};
        float m0 = -1e30f, m1 = -1e30f, l0 = 0.f, l1 = 0.f;

        for (int t0 = start; t0 < end; t0 += 32) {
            // ---- cooperative K/V tile load (tf32; V transposed) ----
            int r  = tid >> 2;
            int c0 = (tid & 3) * 8;
            int j  = t0 + r;
            __syncthreads();
            if (j < end) {
                const float4* kp = (const float4*)&g_k[j * HIDDEN + hh * HEAD_DIM + c0];
                float4 ka = kp[0], kb = kp[1];
                *(uint4*)&Ks[r][c0]     = make_uint4(f2tf(ka.x), f2tf(ka.y), f2tf(ka.z), f2tf(ka.w));
                *(uint4*)&Ks[r][c0 + 4] = make_uint4(f2tf(kb.x), f2tf(kb.y), f2tf(kb.z), f2tf(kb.w));
                const float4* vp = (const float4*)&g_v[j * HIDDEN + hh * HEAD_DIM + c0];
                float4 va = vp[0], vb = vp[1];
                Vt[c0 + 0][r] = f2tf(va.x); Vt[c0 + 1][r] = f2tf(va.y);
                Vt[c0 + 2][r] = f2tf(va.z); Vt[c0 + 3][r] = f2tf(va.w);
                Vt[c0 + 4][r] = f2tf(vb.x); Vt[c0 + 5][r] = f2tf(vb.y);
                Vt[c0 + 6][r] = f2tf(vb.z); Vt[c0 + 7][r] = f2tf(vb.w);
            } else {
                uint4 z = make_uint4(0u, 0u, 0u, 0u);
                *(uint4*)&Ks[r][c0] = z; *(uint4*)&Ks[r][c0 + 4] = z;
                #pragma unroll
                for (int i = 0; i < 8; i++) Vt[c0 + i][r] = 0u;
            }
            __syncthreads();

            // ---- S = Q K^T ----
            float s[4][4] = {};
            #pragma unroll
            for (int fn = 0; fn < 4; fn++) {
                #pragma unroll
                for (int kk = 0; kk < 4; kk++) {
                    uint32_t b[2];
                    b[0] = Ks[fn * 8 + gq][kk * 8 + tq];
                    b[1] = Ks[fn * 8 + gq][kk * 8 + tq + 4];
                    mma_tf32(s[fn], qa[kk], b);
                }
            }

            // ---- mask + scale ----
            int tn = end - t0;
            #pragma unroll
            for (int fn = 0; fn < 4; fn++) {
                int c = fn * 8 + 2 * tq;
                bool ok0 = (c < tn), ok1 = (c + 1 < tn);
                s[fn][0] = ok0 ? s[fn][0] * ATT_SCALE : -1e30f;
                s[fn][1] = ok1 ? s[fn][1] * ATT_SCALE : -1e30f;
                s[fn][2] = ok0 ? s[fn][2] * ATT_SCALE : -1e30f;
                s[fn][3] = ok1 ? s[fn][3] * ATT_SCALE : -1e30f;
            }

            // ---- online softmax (per-row over 4 lanes) ----
            float M0 = -1e30f, M1 = -1e30f;
            #pragma unroll
            for (int fn = 0; fn < 4; fn++) {
                M0 = fmaxf(M0, fmaxf(s[fn][0], s[fn][1]));
                M1 = fmaxf(M1, fmaxf(s[fn][2], s[fn][3]));
            }
            M0 = fmaxf(M0, __shfl_xor_sync(0xffffffffu, M0, 1));
            M0 = fmaxf(M0, __shfl_xor_sync(0xffffffffu, M0, 2));
            M1 = fmaxf(M1, __shfl_xor_sync(0xffffffffu, M1, 1));
            M1 = fmaxf(M1, __shfl_xor_sync(0xffffffffu, M1, 2));
            float nm0 = fmaxf(m0, M0), nm1 = fmaxf(m1, M1);
            float cr0 = __expf(m0 - nm0), cr1 = __expf(m1 - nm1);
            m0 = nm0; m1 = nm1;
            l0 *= cr0; l1 *= cr1;
            #pragma unroll
            for (int fn = 0; fn < 4; fn++) {
                o[fn][0] *= cr0; o[fn][1] *= cr0;
                o[fn][2] *= cr1; o[fn][3] *= cr1;
            }

            // ---- P = exp(S - m); stage to smem as tf32 ----
            #pragma unroll
            for (int fn = 0; fn < 4; fn++) {
                float p0 = __expf(s[fn][0] - m0), p1 = __expf(s[fn][1] - m0);
                float p2 = __expf(s[fn][2] - m1), p3 = __expf(s[fn][3] - m1);
                l0 += p0 + p1; l1 += p2 + p3;
                int c = fn * 8 + 2 * tq;
                Ps[wid][gq][c]     = f2tf(p0);
                Ps[wid][gq][c + 1] = f2tf(p1);
                Ps[wid][gq + 8][c]     = f2tf(p2);
                Ps[wid][gq + 8][c + 1] = f2tf(p3);
            }
            __syncwarp();

            // ---- O += P V ----
            #pragma unroll
            for (int kk = 0; kk < 4; kk++) {
                uint32_t pa[4];
                pa[0] = Ps[wid][gq][kk * 8 + tq];
                pa[1] = Ps[wid][gq + 8][kk * 8 + tq];
                pa[2] = Ps[wid][gq][kk * 8 + tq + 4];
                pa[3] = Ps[wid][gq + 8][kk * 8 + tq + 4];
                #pragma unroll
                for (int fn = 0; fn < 4; fn++) {
                    uint32_t b[2];
                    b[0] = Vt[fn * 8 + gq][kk * 8 + tq];
                    b[1] = Vt[fn * 8 + gq][kk * 8 + tq + 4];
                    mma_tf32(o[fn], pa, b);
                }
            }
        }

        // ---- finalize: reduce l over lane group, normalize, store ----
        l0 += __shfl_xor_sync(0xffffffffu, l0, 1);
        l0 += __shfl_xor_sync(0xffffffffu, l0, 2);
        l1 += __shfl_xor_sync(0xffffffffu, l1, 1);
        l1 += __shfl_xor_sync(0xffffffffu, l1, 2);
        float inv0 = (l0 > 0.f) ? 1.f / l0 : 0.f;
        float inv1 = (l1 > 0.f) ? 1.f / l1 : 0.f;
        #pragma unroll
        for (int fn = 0; fn < 4; fn++) {
            int col = hh * HEAD_DIM + fn * 8 + 2 * tq;
            if (v0) *(float2*)&g_att[r0 * HIDDEN + col] =
                make_float2(o[fn][0] * inv0, o[fn][1] * inv0);
            if (v1) *(float2*)&g_att[r1 * HIDDEN + col] =
                make_float2(o[fn][2] * inv1, o[fn][3] * inv1);
        }
    }
}

// ---------------------------------------------------------------------------
extern "C" void kernel_launch(void* const* d_in, const int* in_sizes, int n_in,
                              void* d_out, int out_size) {
    const float* x     = (const float*)d_in[0];
    const int*   batch = (const int*)  d_in[1];
    const float* Wq    = (const float*)d_in[2];
    const float* bq    = (const float*)d_in[3];
    const float* Wk    = (const float*)d_in[4];
    const float* bk    = (const float*)d_in[5];
    const float* Wv    = (const float*)d_in[6];
    const float* bv    = (const float*)d_in[7];
    const float* Wo    = (const float*)d_in[8];
    const float* bo    = (const float*)d_in[9];
    const float* gamma = (const float*)d_in[10];
    const float* beta  = (const float*)d_in[11];
    float* out = (float*)d_out;

    int n = in_sizes[0] / HIDDEN;   // 4096

    float *ph, *pq, *pk, *pv, *patt;
    cudaGetSymbolAddress((void**)&ph,   g_h);
    cudaGetSymbolAddress((void**)&pq,   g_q);
    cudaGetSymbolAddress((void**)&pk,   g_k);
    cudaGetSymbolAddress((void**)&pv,   g_v);
    cudaGetSymbolAddress((void**)&patt, g_att);

    prep_batch_kernel<<<1, 256>>>(batch, n);
    ln_kernel<<<n, 256>>>(x, gamma, beta, ph);

    dim3 gqkv(HIDDEN / 64, n / 128, 3);
    gemm_qkv_kernel<<<gqkv, 256>>>(ph, Wq, bq, pq, Wk, bk, pk, Wv, bv, pv);

    attn_kernel<<<dim3(NGRAPH, HEADS, 8), 128>>>();

    dim3 go(HIDDEN / 64, n / 128, 1);
    gemm_o_kernel<<<go, 256>>>(patt, Wo, bo, x, out);
}